// round 8
// baseline (speedup 1.0000x reference)
#include <cuda_runtime.h>
#include <stdint.h>

// Problem constants (match reference setup)
#define NN 100000          // N_NODES
#define DIM 256            // DIM_ATTEN
#define DIM4 (DIM / 4)     // float4 per node row (64)
#define HASH_BITS 22
#define HASH_SIZE (1u << HASH_BITS)   // 4,194,304 slots x u32 = 16 MB
#define HASH_MASK (HASH_SIZE - 1u)

#define TOTAL4 ((unsigned)NN * DIM4)  // 6,400,000 float4 in node_feature
#define FUSE_BLK 256
#define FUSE_PER_BLK (FUSE_BLK * 4)   // 1024 float4 per block
#define FUSE_FEAT_BLOCKS (TOTAL4 / FUSE_PER_BLK)  // 6250 exactly

// PDL intrinsics via PTX (no CDP linkage needed)
__device__ __forceinline__ void pdl_trigger() {
    asm volatile("griddepcontrol.launch_dependents;" ::: "memory");
}
__device__ __forceinline__ void pdl_wait() {
    asm volatile("griddepcontrol.wait;" ::: "memory");
}

// Scratch (device globals — no dynamic allocation allowed)
__device__ unsigned int g_hash[HASH_SIZE];   // 0 = empty, else 32-bit fingerprint
__device__ int g_in_deg[NN];
__device__ int g_out_deg[NN];

// ---------------------------------------------------------------------------
// Kernel 1: clear hash table (16 MB) + degree counters.
// Doubles as an L2 prefetch of the hash table for the edge kernel.
// Triggers dependent launch immediately (edge waits via griddepcontrol.wait).
// ---------------------------------------------------------------------------
__global__ void clear_kernel() {
    pdl_trigger();   // let edge_kernel launch & do its independent loads
    const unsigned tid = blockIdx.x * blockDim.x + threadIdx.x;
    const unsigned stride = gridDim.x * blockDim.x;
    uint4* h4 = reinterpret_cast<uint4*>(g_hash);
    const unsigned n4 = HASH_SIZE / 4;           // 1,048,576 uint4 stores
    const uint4 z = make_uint4(0u, 0u, 0u, 0u);
    for (unsigned i = tid; i < n4; i += stride) h4[i] = z;
    for (unsigned i = tid; i < NN; i += stride) {
        g_in_deg[i] = 0;
        g_out_deg[i] = 0;
    }
}

// ---------------------------------------------------------------------------
// Kernel 2: dedup edges via fingerprint hash set (CAS-first probing).
// edge_index is INT32 on device. ONE edge per thread (latency-bound CAS).
// PDL: overlaps index loads + hashing with the clear; waits before first CAS.
// ---------------------------------------------------------------------------
__device__ __forceinline__ unsigned long long mix64(unsigned long long h) {
    h ^= h >> 33;
    h *= 0xff51afd7ed558ccdULL;
    h ^= h >> 33;
    h *= 0xc4ceb9fe1a85ec53ULL;
    h ^= h >> 33;
    return h;
}

__global__ void edge_kernel(const int* __restrict__ edge_index, int n_edges) {
    pdl_trigger();   // let fuse_kernel launch & start its x-stream loads
    const int e = blockIdx.x * blockDim.x + threadIdx.x;
    if (e >= n_edges) { pdl_wait(); return; }

    int s = edge_index[e];            // row 0: src (coalesced, indep of clear)
    int d = edge_index[e + n_edges];  // row 1: dst (coalesced)
    s = min(max(s, 0), NN - 1);
    d = min(max(d, 0), NN - 1);

    const unsigned long long key =
        (unsigned long long)s * (unsigned long long)NN + (unsigned long long)d;
    const unsigned long long h = mix64(key);
    unsigned slot = (unsigned)h & HASH_MASK;
    unsigned fp = (unsigned)(h >> 32);
    if (fp == 0u) fp = 1u;                       // 0 is the empty sentinel

    pdl_wait();      // clear must be complete before touching the hash

    while (true) {
        const unsigned prev = atomicCAS(&g_hash[slot], 0u, fp);
        if (prev == 0u) {                        // first occurrence of this pair
            atomicAdd(&g_in_deg[s], 1);          // REDG, fire-and-forget
            atomicAdd(&g_out_deg[d], 1);
            return;
        }
        if (prev == fp) return;                  // duplicate — drop
        slot = (slot + 1) & HASH_MASK;
    }
}

// ---------------------------------------------------------------------------
// Kernel 3: node_feature = x + in_tbl[in_deg] + out_tbl[out_deg]
// COALESCED ILP: thread handles idx = blk*1024 + tid + k*256 (k=0..3).
// PDL: x loads (102 MB DRAM stream) issue before waiting on edge results.
// Blocks >= FUSE_FEAT_BLOCKS zero the attn_bias tail of d_out.
// ---------------------------------------------------------------------------
__global__ void fuse_kernel(const float4* __restrict__ x,
                            const float4* __restrict__ in_tbl,
                            const float4* __restrict__ out_tbl,
                            float4* __restrict__ out,
                            long long out_elems) {
    const unsigned blk = blockIdx.x;
    if (blk < FUSE_FEAT_BLOCKS) {
        const unsigned base = blk * FUSE_PER_BLK + threadIdx.x;

        unsigned idx[4], node[4], col[4];
        float4 xv[4], a[4], b[4];
#pragma unroll
        for (int k = 0; k < 4; k++) {
            idx[k] = base + k * FUSE_BLK;
            node[k] = idx[k] >> 6;
            col[k]  = idx[k] & 63u;
        }
        // x loads first: independent of edge results — overlap with edge tail
#pragma unroll
        for (int k = 0; k < 4; k++) xv[k] = x[idx[k]];

        pdl_wait();   // degrees valid only after edge_kernel completes

        // degree loads (warp-broadcast, L1/L2-hot) then table gathers
#pragma unroll
        for (int k = 0; k < 4; k++) {
            int di = g_in_deg[node[k]];
            int dd = g_out_deg[node[k]];
            di = min(max(di, 0), 511);
            dd = min(max(dd, 0), 511);
            a[k] = __ldg(&in_tbl[(unsigned)di * DIM4 + col[k]]);
            b[k] = __ldg(&out_tbl[(unsigned)dd * DIM4 + col[k]]);
        }

#pragma unroll
        for (int k = 0; k < 4; k++) {
            float4 r;
            r.x = xv[k].x + a[k].x + b[k].x;
            r.y = xv[k].y + a[k].y + b[k].y;
            r.z = xv[k].z + a[k].z + b[k].z;
            r.w = xv[k].w + a[k].w + b[k].w;
            out[idx[k]] = r;
        }
    } else {
        // tail zeroing: no dependency on edge results, but PDL wait is
        // required semantics-free here; skip it (writes d_out only).
        const long long tail_tid =
            (long long)(blk - FUSE_FEAT_BLOCKS) * FUSE_BLK + threadIdx.x;
        const long long i = (long long)NN * DIM + tail_tid;
        if (i < out_elems) reinterpret_cast<float*>(out)[i] = 0.0f;
    }
}

// ---------------------------------------------------------------------------
// Launch — edge and fuse use programmatic stream serialization (PDL) so their
// independent front-end loads overlap the predecessor kernel's tail.
// Inputs (metadata order):
//   0: x                 [100000, 256] float32
//   1: edge_feature      [1600000, 128] float32 (zeros — unused)
//   2: edge_index        [2, 1600000] int32
//   3: in_degree_table   [512, 256] float32
//   4: out_degree_table  [512, 256] float32
// Output: node_feature   [100000, 256] float32 (+ possible attn_bias tail)
// ---------------------------------------------------------------------------
extern "C" void kernel_launch(void* const* d_in, const int* in_sizes, int n_in,
                              void* d_out, int out_size) {
    const float4* x        = (const float4*)d_in[0];
    const int* ei          = (const int*)d_in[2];
    const float4* in_tbl   = (const float4*)d_in[3];
    const float4* out_tbl  = (const float4*)d_in[4];
    float4* out            = (float4*)d_out;

    const int n_edges = in_sizes[2] / 2;

    // 1) clear scratch (16.8 MB) — also prefetches the hash into L2
    clear_kernel<<<4096, 256>>>();

    // PDL attribute for dependent launches
    cudaLaunchAttribute pdl_attr;
    pdl_attr.id = cudaLaunchAttributeProgrammaticStreamSerialization;
    pdl_attr.val.programmaticStreamSerializationAllowed = 1;

    // 2) dedup + degree count (1 edge/thread), PDL over clear
    {
        cudaLaunchConfig_t cfg = {};
        cfg.gridDim  = dim3((n_edges + 255) / 256);
        cfg.blockDim = dim3(256);
        cfg.attrs = &pdl_attr;
        cfg.numAttrs = 1;
        cfg.stream = 0;  // legacy default stream (same as <<<>>>)
        cudaLaunchKernelEx(&cfg, edge_kernel, ei, n_edges);
    }

    // 3) fused gather-add + tail zero, PDL over edge
    {
        const long long nf_elems = (long long)NN * DIM;   // 25,600,000
        long long extra = (long long)out_size - nf_elems;
        if (extra < 0) extra = 0;
        const unsigned tail_blocks =
            (unsigned)((extra + FUSE_BLK - 1) / FUSE_BLK);
        cudaLaunchConfig_t cfg = {};
        cfg.gridDim  = dim3(FUSE_FEAT_BLOCKS + tail_blocks);
        cfg.blockDim = dim3(FUSE_BLK);
        cfg.attrs = &pdl_attr;
        cfg.numAttrs = 1;
        cfg.stream = 0;
        long long out_elems = (long long)out_size;
        cudaLaunchKernelEx(&cfg, fuse_kernel, x, in_tbl, out_tbl, out, out_elems);
    }
}